// round 6
// baseline (speedup 1.0000x reference)
#include <cuda_runtime.h>
#include <cuda_bf16.h>
#include <cstdint>
#include <math.h>

// ---------------------------------------------------------------------------
// EncoderLayer: B=2, S=2048, D=1024, H=16, dk=64, FF=4096, fp32
// Round 6 (= Round 5 resubmit after infra failure):
//   ldmatrix.x4 fragment loads everywhere, pre-transposed+tf32-rounded
//   weights, K/V tiles pre-converted in smem, V loaded transposed via
//   4-byte cp.async. tf32 numerics identical to Round 4.
// ---------------------------------------------------------------------------

#define D_MODEL 1024
#define SEQ     2048
#define BATCH   2
#define NHEADS  16
#define DK      64
#define DFF     4096
#define MTOT    (BATCH * SEQ)          // 4096 rows

__device__ float g_Q  [MTOT * D_MODEL];
__device__ float g_K  [MTOT * D_MODEL];
__device__ float g_V  [MTOT * D_MODEL];
__device__ float g_ctx[MTOT * D_MODEL];
__device__ float g_t1 [MTOT * D_MODEL];
__device__ float g_x1 [MTOT * D_MODEL];
__device__ float g_h1 [MTOT * DFF];
__device__ float g_t2 [MTOT * D_MODEL];
// Pre-transposed (+tf32-rounded) weights: [N][K] layouts
__device__ float g_Wqt[D_MODEL * D_MODEL];
__device__ float g_Wkt[D_MODEL * D_MODEL];
__device__ float g_Wvt[D_MODEL * D_MODEL];
__device__ float g_Wot[D_MODEL * D_MODEL];
__device__ float g_W1t[DFF * D_MODEL];
__device__ float g_W2t[D_MODEL * DFF];

// ---------------------------------------------------------------------------
// PTX helpers
// ---------------------------------------------------------------------------
__device__ __forceinline__ void cp16(uint32_t saddr, const void* gptr) {
    asm volatile("cp.async.cg.shared.global [%0], [%1], 16;"
                 :: "r"(saddr), "l"(gptr));
}
__device__ __forceinline__ void cp4(uint32_t saddr, const void* gptr) {
    asm volatile("cp.async.ca.shared.global [%0], [%1], 4;"
                 :: "r"(saddr), "l"(gptr));
}
__device__ __forceinline__ uint32_t smem_u32(const void* p) {
    uint32_t a;
    asm("{ .reg .u64 t; cvta.to.shared.u64 t, %1; cvt.u32.u64 %0, t; }"
        : "=r"(a) : "l"(p));
    return a;
}
__device__ __forceinline__ uint32_t to_tf32(float v) {
    uint32_t x;
    asm("cvt.rna.tf32.f32 %0, %1;" : "=r"(x) : "f"(v));
    return x;
}
__device__ __forceinline__ float tf32r(float v) {
    return __uint_as_float(to_tf32(v));
}
#define LDM4(r0, r1, r2, r3, addr) \
    asm volatile("ldmatrix.sync.aligned.m8n8.x4.shared.b16 {%0,%1,%2,%3}, [%4];" \
                 : "=r"(r0), "=r"(r1), "=r"(r2), "=r"(r3) : "r"(addr))
#define MMA_TF32(acc, a0, a1, a2, a3, b0, b1) \
    asm volatile( \
        "mma.sync.aligned.m16n8k8.row.col.f32.tf32.tf32.f32 " \
        "{%0,%1,%2,%3}, {%4,%5,%6,%7}, {%8,%9}, {%0,%1,%2,%3};" \
        : "+f"((acc)[0]), "+f"((acc)[1]), "+f"((acc)[2]), "+f"((acc)[3]) \
        : "r"(a0), "r"(a1), "r"(a2), "r"(a3), "r"(b0), "r"(b1))

// ---------------------------------------------------------------------------
// Weight transpose + tf32 round: in[R][C] -> out[C][R]
// ---------------------------------------------------------------------------
__global__ void __launch_bounds__(256)
transpose_cvt(const float* __restrict__ in, float* __restrict__ out,
              int R, int C)
{
    __shared__ float t[32][33];
    const int tx = threadIdx.x & 31;
    const int ty = threadIdx.x >> 5;          // 0..7
    const int c0 = blockIdx.x * 32;
    const int r0 = blockIdx.y * 32;
#pragma unroll
    for (int i = 0; i < 4; i++) {
        int r = ty + i * 8;
        t[r][tx] = tf32r(in[(size_t)(r0 + r) * C + c0 + tx]);
    }
    __syncthreads();
#pragma unroll
    for (int i = 0; i < 4; i++) {
        int r = ty + i * 8;
        out[(size_t)(c0 + r) * R + r0 + tx] = t[tx][r];
    }
}

// ---------------------------------------------------------------------------
// tf32 MMA GEMM: C[M,N] = act((A[M,K] @ Wt^T + bias)*scale) + residual
// Wt is [N][K] (pre-transposed, tf32-rounded). 128x128x32 tiles, 256 thr.
// ---------------------------------------------------------------------------
#define BM 128
#define BN 128
#define BK 32
#define GP 36                 // smem pitch (floats); ==4 mod 32 banks
#define A_TILE (BM * GP)      // 4608
#define B_TILE (BN * GP)      // 4608
#define GEMM_SMEM_BYTES (2 * (A_TILE + B_TILE) * 4)   // 73728

__global__ void __launch_bounds__(256, 2)
gemm_tc(const float* __restrict__ A, const float* __restrict__ Wt,
        const float* __restrict__ bias, const float* __restrict__ res,
        float* __restrict__ C, int M, int N, int K, float scale, int relu)
{
    extern __shared__ float sm[];
    float* sA[2] = { sm,              sm + A_TILE };
    float* sB[2] = { sm + 2 * A_TILE, sm + 2 * A_TILE + B_TILE };

    const int tid = threadIdx.x;
    const int wid = tid >> 5;
    const int lid = tid & 31;
    const int g   = lid >> 2;
    const int t   = lid & 3;
    const int r8  = lid & 7;
    const int sel = lid >> 3;
    const int wm  = wid >> 2;
    const int wn  = wid & 3;
    const int bm  = blockIdx.y * BM;
    const int bn  = blockIdx.x * BN;
    const int mrow = wm * 64;
    const int ncol = wn * 32;

    float acc[4][4][4];
#pragma unroll
    for (int mi = 0; mi < 4; mi++)
#pragma unroll
        for (int ni = 0; ni < 4; ni++)
#pragma unroll
            for (int c = 0; c < 4; c++) acc[mi][ni][c] = 0.f;

    const uint32_t sA_u[2] = { smem_u32(sA[0]), smem_u32(sA[1]) };
    const uint32_t sB_u[2] = { smem_u32(sB[0]), smem_u32(sB[1]) };

    // ldmatrix lane base offsets (bytes within tile)
    uint32_t aoff[4], boff[2];
#pragma unroll
    for (int mi = 0; mi < 4; mi++)
        aoff[mi] = (uint32_t)(((mrow + mi * 16 + (sel & 1) * 8 + r8) * GP
                              + (sel >> 1) * 4) * 4);
#pragma unroll
    for (int j = 0; j < 2; j++)
        boff[j] = (uint32_t)(((ncol + j * 16 + (sel >> 1) * 8 + r8) * GP
                              + (sel & 1) * 4) * 4);

    auto load_tiles = [&](int buf, int k0) {
#pragma unroll
        for (int l = 0; l < 4; l++) {
            int i  = tid + l * 256;
            int rr = i >> 3;
            int cc = i & 7;
            cp16(sA_u[buf] + (uint32_t)(rr * GP + cc * 4) * 4,
                 A + (size_t)(bm + rr) * K + k0 + cc * 4);
            cp16(sB_u[buf] + (uint32_t)(rr * GP + cc * 4) * 4,
                 Wt + (size_t)(bn + rr) * K + k0 + cc * 4);
        }
    };

    const int niter = K / BK;
    load_tiles(0, 0);
    asm volatile("cp.async.commit_group;" ::: "memory");

    for (int it = 0; it < niter; it++) {
        asm volatile("cp.async.wait_group 0;" ::: "memory");
        __syncthreads();
        if (it + 1 < niter) load_tiles((it + 1) & 1, (it + 1) * BK);
        asm volatile("cp.async.commit_group;" ::: "memory");

        const int buf = it & 1;
        // pre-round A tile to tf32 in place (B already rounded)
        float* Ab = sA[buf];
#pragma unroll
        for (int l = 0; l < 4; l++) {
            int i  = tid + l * 256;
            int rr = i >> 3;
            int cc = i & 7;
            float4* p = (float4*)(Ab + rr * GP + cc * 4);
            float4 v = *p;
            v.x = tf32r(v.x); v.y = tf32r(v.y);
            v.z = tf32r(v.z); v.w = tf32r(v.w);
            *p = v;
        }
        __syncthreads();

        const uint32_t Au = sA_u[buf];
        const uint32_t Bu = sB_u[buf];
#pragma unroll
        for (int kk = 0; kk < 4; kk++) {
            uint32_t af[4][4], bf[4][2];
#pragma unroll
            for (int mi = 0; mi < 4; mi++)
                LDM4(af[mi][0], af[mi][1], af[mi][2], af[mi][3],
                     Au + aoff[mi] + kk * 32);
#pragma unroll
            for (int j = 0; j < 2; j++) {
                uint32_t b0, b1, b2, b3;
                LDM4(b0, b1, b2, b3, Bu + boff[j] + kk * 32);
                bf[2 * j][0] = b0;     bf[2 * j][1] = b1;
                bf[2 * j + 1][0] = b2; bf[2 * j + 1][1] = b3;
            }
#pragma unroll
            for (int mi = 0; mi < 4; mi++)
#pragma unroll
                for (int ni = 0; ni < 4; ni++)
                    MMA_TF32(acc[mi][ni], af[mi][0], af[mi][1], af[mi][2],
                             af[mi][3], bf[ni][0], bf[ni][1]);
        }
    }

    // ---- epilogue -------------------------------------------------------
#pragma unroll
    for (int mi = 0; mi < 4; mi++) {
        const int r0 = bm + wm * 64 + mi * 16 + g;
        const int r1 = r0 + 8;
#pragma unroll
        for (int ni = 0; ni < 4; ni++) {
            const int c0 = bn + wn * 32 + ni * 8 + 2 * t;
            const float b0 = bias[c0], b1 = bias[c0 + 1];

            float v00 = (acc[mi][ni][0] + b0) * scale;
            float v01 = (acc[mi][ni][1] + b1) * scale;
            float v10 = (acc[mi][ni][2] + b0) * scale;
            float v11 = (acc[mi][ni][3] + b1) * scale;
            if (relu) {
                v00 = fmaxf(v00, 0.f); v01 = fmaxf(v01, 0.f);
                v10 = fmaxf(v10, 0.f); v11 = fmaxf(v11, 0.f);
            }
            if (res) {
                float2 q0 = *(const float2*)(res + (size_t)r0 * N + c0);
                float2 q1 = *(const float2*)(res + (size_t)r1 * N + c0);
                v00 += q0.x; v01 += q0.y; v10 += q1.x; v11 += q1.y;
            }
            *(float2*)(C + (size_t)r0 * N + c0) = make_float2(v00, v01);
            *(float2*)(C + (size_t)r1 * N + c0) = make_float2(v10, v11);
        }
    }
}

// ---------------------------------------------------------------------------
// Flash attention, ldmatrix edition.
// CTA: 128 queries x 64-key tiles, 8 warps (16 Q rows each).
// sK [key][dk] (cvt'd in place), sVt [dk][key] (loaded transposed via cp4,
// cvt'd in place), sP [q][key] stores tf32-rounded probabilities.
// ---------------------------------------------------------------------------
#define FBQ 128
#define FBK 64
#define FPCH 68               // ==4 mod 32 banks, 16B-aligned rows
#define KV_TILE (FBK * FPCH)  // 4352 floats
#define FLASH_SMEM ((4 * KV_TILE + FBQ * FPCH) * 4)   // 104448 B

__global__ void __launch_bounds__(256, 1)
flash_tc(const float* __restrict__ Qg, const float* __restrict__ Kg,
         const float* __restrict__ Vg, float* __restrict__ ctx)
{
    extern __shared__ float fs[];
    float* sK [2] = { fs,               fs + KV_TILE };
    float* sVt[2] = { fs + 2 * KV_TILE, fs + 3 * KV_TILE };
    float* sP     = fs + 4 * KV_TILE;

    const int tid = threadIdx.x;
    const int wid = tid >> 5;
    const int lid = tid & 31;
    const int g   = lid >> 2;
    const int t   = lid & 3;
    const int r8  = lid & 7;
    const int sel = lid >> 3;
    const int qb  = blockIdx.x;
    const int h   = blockIdx.y;
    const int b   = blockIdx.z;
    const int qrow = wid * 16;

    const size_t baseQ  = ((size_t)b * SEQ + (size_t)qb * FBQ) * D_MODEL + h * DK;
    const size_t baseKV = ((size_t)b * SEQ) * D_MODEL + h * DK;

    const uint32_t sK_u [2] = { smem_u32(sK[0]),  smem_u32(sK[1]) };
    const uint32_t sVt_u[2] = { smem_u32(sVt[0]), smem_u32(sVt[1]) };
    const uint32_t sP_u     = smem_u32(sP);

    // ldmatrix lane offsets (bytes)
    uint32_t koff[4], voff[4];
#pragma unroll
    for (int j = 0; j < 4; j++) {
        uint32_t row = (uint32_t)((2 * j + (sel >> 1)) * 8 + r8);
        koff[j] = (row * FPCH + (sel & 1) * 4) * 4;
        voff[j] = koff[j];
    }
    const uint32_t poff =
        (uint32_t)(((qrow + (sel & 1) * 8 + r8) * FPCH + (sel >> 1) * 4) * 4);

    // ---- stage Q through sP, build tf32 register fragments --------------
    for (int l = 0; l < 8; l++) {
        int i  = tid + l * 256;
        int rr = i >> 4;
        int cc = i & 15;
        float4 v = *(const float4*)(Qg + baseQ + (size_t)rr * D_MODEL + cc * 4);
        *(float4*)(&sP[rr * FPCH + cc * 4]) = v;
    }
    __syncthreads();

    uint32_t qf[8][4];
#pragma unroll
    for (int kb = 0; kb < 8; kb++) {
        uint32_t q0, q1, q2, q3;
        LDM4(q0, q1, q2, q3, sP_u + poff + kb * 32);
        qf[kb][0] = to_tf32(__uint_as_float(q0));
        qf[kb][1] = to_tf32(__uint_as_float(q1));
        qf[kb][2] = to_tf32(__uint_as_float(q2));
        qf[kb][3] = to_tf32(__uint_as_float(q3));
    }
    __syncthreads();

    float m0 = -1e30f, m1 = -1e30f, l0 = 0.f, l1 = 0.f;
    float oacc[8][4];
#pragma unroll
    for (int ni = 0; ni < 8; ni++)
#pragma unroll
        for (int c = 0; c < 4; c++) oacc[ni][c] = 0.f;

    const int vkey = tid & 63;           // cp4 loader mapping
    const int vdkb = tid >> 6;

    auto load_kv = [&](int buf, int k0) {
#pragma unroll
        for (int l = 0; l < 4; l++) {
            int i  = tid + l * 256;
            int rr = i >> 4;
            int cc = i & 15;
            cp16(sK_u[buf] + (uint32_t)(rr * FPCH + cc * 4) * 4,
                 Kg + baseKV + (size_t)(k0 + rr) * D_MODEL + cc * 4);
        }
        const float* vg = Vg + baseKV + (size_t)(k0 + vkey) * D_MODEL;
#pragma unroll
        for (int i = 0; i < 16; i++) {
            int dk = vdkb + 4 * i;
            cp4(sVt_u[buf] + (uint32_t)(dk * FPCH + vkey) * 4, vg + dk);
        }
    };

    const int nkt = SEQ / FBK;
    load_kv(0, 0);
    asm volatile("cp.async.commit_group;" ::: "memory");

    for (int kt = 0; kt < nkt; kt++) {
        asm volatile("cp.async.wait_group 0;" ::: "memory");
        __syncthreads();
        if (kt + 1 < nkt) load_kv((kt + 1) & 1, (kt + 1) * FBK);
        asm volatile("cp.async.commit_group;" ::: "memory");

        const int buf = kt & 1;
        // pre-round K and V tiles to tf32 in place
        {
            float* Kb = sK[buf];
            float* Vb = sVt[buf];
#pragma unroll
            for (int l = 0; l < 4; l++) {
                int i  = tid + l * 256;
                int rr = i >> 4;
                int cc = i & 15;
                float4* p = (float4*)(Kb + rr * FPCH + cc * 4);
                float4 v = *p;
                v.x = tf32r(v.x); v.y = tf32r(v.y);
                v.z = tf32r(v.z); v.w = tf32r(v.w);
                *p = v;
                float4* q = (float4*)(Vb + rr * FPCH + cc * 4);
                float4 w = *q;
                w.x = tf32r(w.x); w.y = tf32r(w.y);
                w.z = tf32r(w.z); w.w = tf32r(w.w);
                *q = w;
            }
        }
        __syncthreads();

        const uint32_t Ku = sK_u[buf];
        const uint32_t Vu = sVt_u[buf];

        // ---- S = Q @ K^T ------------------------------------------------
        float sacc[8][4];
#pragma unroll
        for (int ni = 0; ni < 8; ni++)
#pragma unroll
            for (int c = 0; c < 4; c++) sacc[ni][c] = 0.f;

#pragma unroll
        for (int kb = 0; kb < 8; kb++) {
#pragma unroll
            for (int j = 0; j < 4; j++) {
                uint32_t b0, b1, b2, b3;
                LDM4(b0, b1, b2, b3, Ku + koff[j] + kb * 32);
                MMA_TF32(sacc[2 * j],     qf[kb][0], qf[kb][1], qf[kb][2],
                         qf[kb][3], b0, b1);
                MMA_TF32(sacc[2 * j + 1], qf[kb][0], qf[kb][1], qf[kb][2],
                         qf[kb][3], b2, b3);
            }
        }

        // ---- online softmax --------------------------------------------
        float mx0 = -1e30f, mx1 = -1e30f;
#pragma unroll
        for (int ni = 0; ni < 8; ni++) {
            mx0 = fmaxf(mx0, fmaxf(sacc[ni][0], sacc[ni][1]));
            mx1 = fmaxf(mx1, fmaxf(sacc[ni][2], sacc[ni][3]));
        }
        mx0 = fmaxf(mx0, __shfl_xor_sync(0xFFFFFFFFu, mx0, 1));
        mx0 = fmaxf(mx0, __shfl_xor_sync(0xFFFFFFFFu, mx0, 2));
        mx1 = fmaxf(mx1, __shfl_xor_sync(0xFFFFFFFFu, mx1, 1));
        mx1 = fmaxf(mx1, __shfl_xor_sync(0xFFFFFFFFu, mx1, 2));

        const float mn0 = fmaxf(m0, mx0);
        const float mn1 = fmaxf(m1, mx1);
        const float al0 = __expf(m0 - mn0);
        const float al1 = __expf(m1 - mn1);
        m0 = mn0; m1 = mn1;

        float s0 = 0.f, s1 = 0.f;
#pragma unroll
        for (int ni = 0; ni < 8; ni++) {
            float p00 = tf32r(__expf(sacc[ni][0] - mn0));
            float p01 = tf32r(__expf(sacc[ni][1] - mn0));
            float p10 = tf32r(__expf(sacc[ni][2] - mn1));
            float p11 = tf32r(__expf(sacc[ni][3] - mn1));
            s0 += p00 + p01;
            s1 += p10 + p11;
            *(float2*)(&sP[(qrow + g) * FPCH + ni * 8 + 2 * t]) =
                make_float2(p00, p01);
            *(float2*)(&sP[(qrow + g + 8) * FPCH + ni * 8 + 2 * t]) =
                make_float2(p10, p11);
        }
        s0 += __shfl_xor_sync(0xFFFFFFFFu, s0, 1);
        s0 += __shfl_xor_sync(0xFFFFFFFFu, s0, 2);
        s1 += __shfl_xor_sync(0xFFFFFFFFu, s1, 1);
        s1 += __shfl_xor_sync(0xFFFFFFFFu, s1, 2);
        l0 = l0 * al0 + s0;
        l1 = l1 * al1 + s1;

#pragma unroll
        for (int ni = 0; ni < 8; ni++) {
            oacc[ni][0] *= al0; oacc[ni][1] *= al0;
            oacc[ni][2] *= al1; oacc[ni][3] *= al1;
        }
        __syncwarp();

        // ---- O += P @ V -------------------------------------------------
#pragma unroll
        for (int kb = 0; kb < 8; kb++) {
            uint32_t a0, a1, a2, a3;
            LDM4(a0, a1, a2, a3, sP_u + poff + kb * 32);
#pragma unroll
            for (int j = 0; j < 4; j++) {
                uint32_t v0, v1, v2, v3;
                LDM4(v0, v1, v2, v3, Vu + voff[j] + kb * 32);
                MMA_TF32(oacc[2 * j],     a0, a1, a2, a3, v0, v1);
                MMA_TF32(oacc[2 * j + 1], a0, a1, a2, a3, v2, v3);
            }
        }
        __syncwarp();
    }

    // ---- epilogue -------------------------------------------------------
    const float inv0 = 1.f / l0;
    const float inv1 = 1.f / l1;
#pragma unroll
    for (int ni = 0; ni < 8; ni++) {
        const int c0 = ni * 8 + 2 * t;
        *(float2*)(ctx + baseQ + (size_t)(qrow + g) * D_MODEL + c0) =
            make_float2(oacc[ni][0] * inv0, oacc[ni][1] * inv0);
        *(float2*)(ctx + baseQ + (size_t)(qrow + g + 8) * D_MODEL + c0) =
            make_float2(oacc[ni][2] * inv1, oacc[ni][3] * inv1);
    }
}

// ---------------------------------------------------------------------------
// LayerNorm over last dim (1024). One block (256 threads) per row.
// ---------------------------------------------------------------------------
__global__ void __launch_bounds__(256)
ln_kernel(const float* __restrict__ x, const float* __restrict__ g,
          const float* __restrict__ bb, float* __restrict__ out)
{
    const int row = blockIdx.x;
    const int tid = threadIdx.x;
    const float4 v = ((const float4*)(x + (size_t)row * D_MODEL))[tid];

    float s  = v.x + v.y + v.z + v.w;
    float ss = fmaf(v.x, v.x, fmaf(v.y, v.y, fmaf(v.z, v.z, v.w * v.w)));

    __shared__ float rs[8], rss[8];
#pragma unroll
    for (int o = 16; o > 0; o >>= 1) {
        s  += __shfl_down_sync(0xFFFFFFFFu, s, o);
        ss += __shfl_down_sync(0xFFFFFFFFu, ss, o);
    }
    if ((tid & 31) == 0) { rs[tid >> 5] = s; rss[tid >> 5] = ss; }
    __syncthreads();
    if (tid == 0) {
        float S = 0.f, SS = 0.f;
#pragma unroll
        for (int i = 0; i < 8; i++) { S += rs[i]; SS += rss[i]; }
        rs[0] = S; rss[0] = SS;
    }
    __syncthreads();

    const float mu  = rs[0] * (1.f / D_MODEL);
    const float var = rss[0] * (1.f / D_MODEL) - mu * mu;
    const float inv = rsqrtf(var + 1e-5f);

    const float4 g4 = ((const float4*)g)[tid];
    const float4 b4 = ((const float4*)bb)[tid];
    float4 o4;
    o4.x = (v.x - mu) * inv * g4.x + b4.x;
    o4.y = (v.y - mu) * inv * g4.y + b4.y;
    o4.z = (v.z - mu) * inv * g4.z + b4.z;
    o4.w = (v.w - mu) * inv * g4.w + b4.w;
    ((float4*)(out + (size_t)row * D_MODEL))[tid] = o4;
}

// ---------------------------------------------------------------------------
// Launcher
// ---------------------------------------------------------------------------
extern "C" void kernel_launch(void* const* d_in, const int* in_sizes, int n_in,
                              void* d_out, int out_size)
{
    const float* src   = (const float*)d_in[0];
    const float* Wq    = (const float*)d_in[1];
    const float* bq    = (const float*)d_in[2];
    const float* Wk    = (const float*)d_in[3];
    const float* bk    = (const float*)d_in[4];
    const float* Wv    = (const float*)d_in[5];
    const float* bv    = (const float*)d_in[6];
    const float* Wo    = (const float*)d_in[7];
    const float* bo    = (const float*)d_in[8];
    const float* W1    = (const float*)d_in[9];
    const float* b1    = (const float*)d_in[10];
    const float* W2    = (const float*)d_in[11];
    const float* b2    = (const float*)d_in[12];
    const float* ln1g  = (const float*)d_in[13];
    const float* ln1b  = (const float*)d_in[14];
    const float* ln2g  = (const float*)d_in[15];
    const float* ln2b  = (const float*)d_in[16];
    float* out = (float*)d_out;

    float *Q, *K, *V, *ctx, *t1, *x1, *h1, *t2;
    float *Wqt, *Wkt, *Wvt, *Wot, *W1t, *W2t;
    cudaGetSymbolAddress((void**)&Q,   g_Q);
    cudaGetSymbolAddress((void**)&K,   g_K);
    cudaGetSymbolAddress((void**)&V,   g_V);
    cudaGetSymbolAddress((void**)&ctx, g_ctx);
    cudaGetSymbolAddress((void**)&t1,  g_t1);
    cudaGetSymbolAddress((void**)&x1,  g_x1);
    cudaGetSymbolAddress((void**)&h1,  g_h1);
    cudaGetSymbolAddress((void**)&t2,  g_t2);
    cudaGetSymbolAddress((void**)&Wqt, g_Wqt);
    cudaGetSymbolAddress((void**)&Wkt, g_Wkt);
    cudaGetSymbolAddress((void**)&Wvt, g_Wvt);
    cudaGetSymbolAddress((void**)&Wot, g_Wot);
    cudaGetSymbolAddress((void**)&W1t, g_W1t);
    cudaGetSymbolAddress((void**)&W2t, g_W2t);

    cudaFuncSetAttribute(gemm_tc,
                         cudaFuncAttributeMaxDynamicSharedMemorySize, GEMM_SMEM_BYTES);
    cudaFuncSetAttribute(flash_tc,
                         cudaFuncAttributeMaxDynamicSharedMemorySize, FLASH_SMEM);

    // Weight transposes (+tf32 rounding), once per launch
    transpose_cvt<<<dim3(32, 32), 256>>>(Wq, Wqt, D_MODEL, D_MODEL);
    transpose_cvt<<<dim3(32, 32), 256>>>(Wk, Wkt, D_MODEL, D_MODEL);
    transpose_cvt<<<dim3(32, 32), 256>>>(Wv, Wvt, D_MODEL, D_MODEL);
    transpose_cvt<<<dim3(32, 32), 256>>>(Wo, Wot, D_MODEL, D_MODEL);
    transpose_cvt<<<dim3(128, 32), 256>>>(W1, W1t, D_MODEL, DFF);
    transpose_cvt<<<dim3(32, 128), 256>>>(W2, W2t, DFF, D_MODEL);

    const float qscale = 0.125f;  // 1/sqrt(64)

    dim3 gProj(D_MODEL / BN, MTOT / BM);   // (8, 32)
    dim3 gFF1 (DFF / BN,     MTOT / BM);   // (32, 32)

    gemm_tc<<<gProj, 256, GEMM_SMEM_BYTES>>>(src, Wqt, bq, nullptr, Q, MTOT, D_MODEL, D_MODEL, qscale, 0);
    gemm_tc<<<gProj, 256, GEMM_SMEM_BYTES>>>(src, Wkt, bk, nullptr, K, MTOT, D_MODEL, D_MODEL, 1.f, 0);
    gemm_tc<<<gProj, 256, GEMM_SMEM_BYTES>>>(src, Wvt, bv, nullptr, V, MTOT, D_MODEL, D_MODEL, 1.f, 0);

    dim3 gAtt(SEQ / FBQ, NHEADS, BATCH);   // (16, 16, 2)
    flash_tc<<<gAtt, 256, FLASH_SMEM>>>(Q, K, V, ctx);

    gemm_tc<<<gProj, 256, GEMM_SMEM_BYTES>>>(ctx, Wot, bo, src, t1, MTOT, D_MODEL, D_MODEL, 1.f, 0);
    ln_kernel<<<MTOT, 256>>>(t1, ln1g, ln1b, x1);

    gemm_tc<<<gFF1, 256, GEMM_SMEM_BYTES>>>(x1, W1t, b1, nullptr, h1, MTOT, DFF, D_MODEL, 1.f, 1);
    gemm_tc<<<gProj, 256, GEMM_SMEM_BYTES>>>(h1, W2t, b2, x1, t2, MTOT, D_MODEL, DFF, 1.f, 0);
    ln_kernel<<<MTOT, 256>>>(t2, ln2g, ln2b, out);
}